// round 8
// baseline (speedup 1.0000x reference)
#include <cuda_runtime.h>
#include <cuda_bf16.h>
#include <cstdint>

// Problem constants
#define M_Q 65536
#define N_K 65536
#define KNB 16
#define CH  64
#define WST 68

// ---------------------------------------------------------------------------
// Device-global scratch
// ---------------------------------------------------------------------------
__device__ float g_A  [CH * CH];
__device__ float g_QG [M_Q * CH];
__device__ float g_KG [N_K * CH];
__device__ float g_RES[M_Q * CH];
__device__ int   g_mask_mode;
// B fragments: [nb(8)][gemm(2)][lane(32)][16 words]; w: split=w>>3, kb=(w>>1)&3, r=w&1
__device__ unsigned int g_BF[8 * 2 * 32 * 16];

#define SWZ128(x) ((x) ^ (((x) >> 3) & 0x70))

// ---------------------------------------------------------------------------
// fp32x2 helpers
// ---------------------------------------------------------------------------
__device__ __forceinline__ unsigned long long fma2(unsigned long long a,
                                                   unsigned long long b,
                                                   unsigned long long c) {
    unsigned long long d;
    asm("fma.rn.f32x2 %0, %1, %2, %3;" : "=l"(d) : "l"(a), "l"(b), "l"(c));
    return d;
}
__device__ __forceinline__ float hsum2(unsigned long long v) {
    float lo, hi;
    asm("mov.b64 {%0, %1}, %2;" : "=f"(lo), "=f"(hi) : "l"(v));
    return lo + hi;
}

// ---------------------------------------------------------------------------
// bf16 split helpers
// ---------------------------------------------------------------------------
__device__ __forceinline__ unsigned int pack_hi(float x0, float x1,
                                                float& r0, float& r1) {
    __nv_bfloat16 b0 = __float2bfloat16(x0), b1 = __float2bfloat16(x1);
    r0 = x0 - __bfloat162float(b0);
    r1 = x1 - __bfloat162float(b1);
    return ((unsigned int)__bfloat16_as_ushort(b1) << 16) |
           (unsigned int)__bfloat16_as_ushort(b0);
}
__device__ __forceinline__ unsigned int pack_lo(float r0, float r1) {
    return ((unsigned int)__bfloat16_as_ushort(__float2bfloat16(r1)) << 16) |
           (unsigned int)__bfloat16_as_ushort(__float2bfloat16(r0));
}

// ---------------------------------------------------------------------------
// mma.sync / ldmatrix wrappers
// ---------------------------------------------------------------------------
__device__ __forceinline__ uint32_t smem_u32(const void* p) {
    uint32_t a;
    asm("{ .reg .u64 t; cvta.to.shared.u64 t, %1; cvt.u32.u64 %0, t; }"
        : "=r"(a) : "l"(p));
    return a;
}
__device__ __forceinline__ void ldsm_x4(uint32_t& a0, uint32_t& a1,
                                        uint32_t& a2, uint32_t& a3, uint32_t addr) {
    asm volatile("ldmatrix.sync.aligned.m8n8.x4.shared.b16 {%0,%1,%2,%3}, [%4];"
                 : "=r"(a0), "=r"(a1), "=r"(a2), "=r"(a3) : "r"(addr));
}
__device__ __forceinline__ void mma16816(float& c0, float& c1, float& c2, float& c3,
                                         uint32_t a0, uint32_t a1, uint32_t a2,
                                         uint32_t a3, uint32_t b0, uint32_t b1) {
    asm volatile(
        "mma.sync.aligned.m16n8k16.row.col.f32.bf16.bf16.f32 "
        "{%0,%1,%2,%3}, {%4,%5,%6,%7}, {%8,%9}, {%0,%1,%2,%3};"
        : "+f"(c0), "+f"(c1), "+f"(c2), "+f"(c3)
        : "r"(a0), "r"(a1), "r"(a2), "r"(a3), "r"(b0), "r"(b1));
}

// ---------------------------------------------------------------------------
// Kernel 0: detect mask dtype
// ---------------------------------------------------------------------------
__global__ void detect_mask_kernel(const unsigned char* __restrict__ mask) {
    __shared__ int sA, sB;
    int tid = threadIdx.x;
    if (tid == 0) { sA = 0; sB = 0; }
    __syncthreads();
    const uint4* p = (const uint4*)mask;
    int nvec = (M_Q * KNB) / 16;
    int fA = 0, fB = 0;
    for (int i = tid; i < nvec; i += blockDim.x) {
        uint4 v = p[i];
        unsigned w[4] = {v.x, v.y, v.z, v.w};
#pragma unroll
        for (int j = 0; j < 4; j++) {
            if ((w[j] >> 24) == 0x3fu) fA = 1;
            if (w[j] & 0x00ffff00u)    fB = 1;
            if ((w[j] >> 24) && ((w[j] >> 24) != 0x3fu)) fB = 1;
        }
    }
    if (fA) atomicOr(&sA, 1);
    if (fB) atomicOr(&sB, 1);
    __syncthreads();
    if (tid == 0) g_mask_mode = sA ? 2 : (sB ? 0 : 1);
}

// ---------------------------------------------------------------------------
// Kernel 1: A = Wqk @ Wg1
// ---------------------------------------------------------------------------
__global__ void compute_A_kernel(const float* __restrict__ Wqk,
                                 const float* __restrict__ Wg1) {
    int t = blockIdx.x * blockDim.x + threadIdx.x;
    int r = t >> 6, c = t & 63;
    float s = 0.f;
#pragma unroll
    for (int u = 0; u < CH; u++) s += Wqk[r * CH + u] * Wg1[u * CH + c];
    g_A[t] = s;
}

// ---------------------------------------------------------------------------
// Kernel 1b: precompute B fragments (hi/lo split) for Wg2 and Wv
// ---------------------------------------------------------------------------
__global__ void prep_bfrag_kernel(const float* __restrict__ Wg2,
                                  const float* __restrict__ Wv) {
    int idx = blockIdx.x * 256 + threadIdx.x;       // 0..8191
    int nb   = idx >> 10;
    int rem  = idx & 1023;
    int gm   = rem >> 9;
    int rem2 = rem & 511;
    int lane = rem2 >> 4;
    int w    = rem2 & 15;
    int split = w >> 3, kb = (w >> 1) & 3, r = w & 1;
    int t = lane & 3, gg = lane >> 2;
    int k0 = kb * 16 + 2 * t + (r ? 8 : 0);
    int n  = nb * 8 + gg;
    const float* W = gm ? Wv : Wg2;
    float w0 = W[k0 * CH + n];
    float w1 = W[(k0 + 1) * CH + n];
    unsigned int word;
    if (split == 0) { float r0, r1; word = pack_hi(w0, w1, r0, r1); }
    else {
        __nv_bfloat16 b0 = __float2bfloat16(w0), b1 = __float2bfloat16(w1);
        word = pack_lo(w0 - __bfloat162float(b0), w1 - __bfloat162float(b1));
    }
    g_BF[idx] = word;
}

// ---------------------------------------------------------------------------
// Kernel 2: merged projection (fma2 path, unchanged)
// ---------------------------------------------------------------------------
__global__ __launch_bounds__(256) void project_kernel(
    const float* __restrict__ q, const float* __restrict__ q_pos,
    const float* __restrict__ k, const float* __restrict__ k_pos,
    const float* __restrict__ bg1)
{
    __shared__ __align__(16) float AT[CH * WST];
    __shared__ __align__(16) float rowbuf[8][8 * CH];
    __shared__ float bsh[CH];

    int tid = threadIdx.x, lane = tid & 31, wid = tid >> 5;

    for (int i = tid; i < CH * CH; i += 256) {
        int t = i >> 6, c = i & 63;
        AT[c * WST + t] = g_A[i];
    }
    if (tid < CH) bsh[tid] = bg1[tid];
    __syncthreads();

    int row0 = blockIdx.x * 64 + wid * 8;
    bool is_q = row0 < M_Q;
    const float* src = is_q ? q : k;
    const float* pos = is_q ? q_pos : k_pos;
    float* dst       = is_q ? g_QG : g_KG;
    int r0 = is_q ? row0 : row0 - M_Q;

    float* rb = &rowbuf[wid][0];
#pragma unroll
    for (int j = 0; j < 8; j++) {
        const float2* s2 = (const float2*)(src + (size_t)(r0 + j) * CH);
        const float2* p2 = (const float2*)(pos + (size_t)(r0 + j) * CH);
        float2 a = s2[lane], b = p2[lane];
        ((float2*)(rb + j * CH))[lane] = make_float2(a.x + b.x, a.y + b.y);
    }
    __syncwarp();

    unsigned long long accA[8], accB[8];
#pragma unroll
    for (int j = 0; j < 8; j++) { accA[j] = 0ull; accB[j] = 0ull; }
    const float* wr0 = AT + lane * WST;
    const float* wr1 = AT + (lane + 32) * WST;

#pragma unroll
    for (int t4 = 0; t4 < CH; t4 += 4) {
        ulonglong2 wa = *reinterpret_cast<const ulonglong2*>(wr0 + t4);
        ulonglong2 wb = *reinterpret_cast<const ulonglong2*>(wr1 + t4);
#pragma unroll
        for (int j = 0; j < 8; j++) {
            ulonglong2 hp = *reinterpret_cast<const ulonglong2*>(rb + j * CH + t4);
            accA[j] = fma2(hp.x, wa.x, accA[j]);
            accA[j] = fma2(hp.y, wa.y, accA[j]);
            accB[j] = fma2(hp.x, wb.x, accB[j]);
            accB[j] = fma2(hp.y, wb.y, accB[j]);
        }
    }
    float b0 = is_q ? bsh[lane] : 0.f;
    float b1 = is_q ? bsh[lane + 32] : 0.f;
#pragma unroll
    for (int j = 0; j < 8; j++) {
        dst[(size_t)(r0 + j) * CH + lane]      = hsum2(accA[j]) + b0;
        dst[(size_t)(r0 + j) * CH + 32 + lane] = hsum2(accB[j]) + b1;
    }
}

// ---------------------------------------------------------------------------
// Kernel 3: HMMA attention, 2-D warp decomposition.
//   Warp = (m-group mg of 2 m-blocks, n-group ng of 4 n-blocks).
//   A tiles (h and value, hi+lo) all built upfront -> ONE __syncthreads.
//   GEMM1 logits -> D1 smem buffer; GEMM2 + fused softmax epilogue.
// smem: h_hi 16K | h_lo 16K | v_hi 16K | v_lo 16K | mask 512 | D1buf 32K
// ---------------------------------------------------------------------------
#define SM_HH 0
#define SM_HL 16384
#define SM_VH 32768
#define SM_VL 49152
#define SM_MK 65536
#define SM_D1 66048
#define ATT_SMEM (66048 + 32768)

__global__ __launch_bounds__(256, 2) void attn_mma_kernel(
    const float* __restrict__ value, const unsigned char* __restrict__ mask,
    const int* __restrict__ knn, const float* __restrict__ bv)
{
    extern __shared__ __align__(1024) char smc[];
    int*   smask = (int*)(smc + SM_MK);
    float* d1buf = (float*)(smc + SM_D1);

    int tid = threadIdx.x, lane = tid & 31, wid = tid >> 5;
    int m0 = blockIdx.x * 8;
    int t = lane & 3, gg = lane >> 2;

    uint32_t sb_hh = smem_u32(smc + SM_HH);
    uint32_t sb_hl = smem_u32(smc + SM_HL);
    uint32_t sb_vh = smem_u32(smc + SM_VH);
    uint32_t sb_vl = smem_u32(smc + SM_VL);

    // ---- mask preload ----
    if (tid < 128) {
        int qloc = tid >> 4, e = tid & 15;
        size_t ix = (size_t)(m0 + qloc) * KNB + e;
        int mmode = g_mask_mode, mk;
        if (mmode == 0)      mk = mask[ix] != 0;
        else if (mmode == 1) mk = ((const int*)mask)[ix] != 0;
        else                 mk = ((const float*)mask)[ix] != 0.f;
        smask[tid] = mk;
    }

    // ---- build h AND value tiles upfront (warp w = query w) ----
    int mq = m0 + wid;
    int nbr = 0;
    if (lane < KNB) nbr = knn[(size_t)M_Q * KNB + (size_t)mq * KNB + lane];
    float2 qg = ((const float2*)(g_QG + (size_t)mq * CH))[lane];

#pragma unroll
    for (int e = 0; e < KNB; e++) {
        int n = __shfl_sync(0xffffffffu, nbr, e);
        float2 kg = ((const float2*)(g_KG + (size_t)n * CH))[lane];
        float x0 = fmaxf(qg.x - kg.x, 0.f), x1 = fmaxf(qg.y - kg.y, 0.f);
        unsigned off = SWZ128((unsigned)((wid * KNB + e) * 128 + lane * 4));
        float r0, r1;
        unsigned hiw = pack_hi(x0, x1, r0, r1);
        *(unsigned*)(smc + SM_HH + off) = hiw;
        *(unsigned*)(smc + SM_HL + off) = pack_lo(r0, r1);
    }
#pragma unroll
    for (int e = 0; e < KNB; e++) {
        float2 v2 = ((const float2*)(value + ((size_t)mq * KNB + e) * CH))[lane];
        unsigned off = SWZ128((unsigned)((wid * KNB + e) * 128 + lane * 4));
        float r0, r1;
        unsigned hiw = pack_hi(v2.x, v2.y, r0, r1);
        *(unsigned*)(smc + SM_VH + off) = hiw;
        *(unsigned*)(smc + SM_VL + off) = pack_lo(r0, r1);
    }
    __syncthreads();

    int mg = wid >> 1;       // m-group: m-blocks {2mg, 2mg+1}
    int ng = wid & 1;        // n-group: n-blocks [4ng, 4ng+4)

    unsigned lmrow = (unsigned)(lane & 15);
    unsigned lmcol = (unsigned)((lane >> 4) & 1) * 16;

    uint32_t BH[4][8], BL[4][8];

    // ---- load B fragments for GEMM1 (Wg2), 4 owned n-blocks ----
#pragma unroll
    for (int nb = 0; nb < 4; nb++) {
        const uint4* bp = (const uint4*)g_BF + ((size_t)((ng * 4 + nb) * 2 + 0) * 32 + lane) * 4;
        uint4 q0 = bp[0], q1 = bp[1], q2 = bp[2], q3 = bp[3];
        BH[nb][0]=q0.x; BH[nb][1]=q0.y; BH[nb][2]=q0.z; BH[nb][3]=q0.w;
        BH[nb][4]=q1.x; BH[nb][5]=q1.y; BH[nb][6]=q1.z; BH[nb][7]=q1.w;
        BL[nb][0]=q2.x; BL[nb][1]=q2.y; BL[nb][2]=q2.z; BL[nb][3]=q2.w;
        BL[nb][4]=q3.x; BL[nb][5]=q3.y; BL[nb][6]=q3.z; BL[nb][7]=q3.w;
    }

    // ---- GEMM1: logits -> D1 smem buffer ----
#pragma unroll
    for (int mbi = 0; mbi < 2; mbi++) {
        int b = mg * 2 + mbi;
        float c[4][4];
#pragma unroll
        for (int nb = 0; nb < 4; nb++)
#pragma unroll
            for (int j = 0; j < 4; j++) c[nb][j] = 0.f;
        unsigned rowoff = (unsigned)(b * 16 + lmrow) * 128 + lmcol;
#pragma unroll
        for (int kb = 0; kb < 4; kb++) {
            unsigned off = SWZ128(rowoff + kb * 32);
            uint32_t a0, a1, a2, a3, l0, l1, l2, l3;
            ldsm_x4(a0, a1, a2, a3, sb_hh + off);
            ldsm_x4(l0, l1, l2, l3, sb_hl + off);
#pragma unroll
            for (int nb = 0; nb < 4; nb++) {
                mma16816(c[nb][0], c[nb][1], c[nb][2], c[nb][3],
                         a0, a1, a2, a3, BH[nb][kb*2], BH[nb][kb*2+1]);
                mma16816(c[nb][0], c[nb][1], c[nb][2], c[nb][3],
                         a0, a1, a2, a3, BL[nb][kb*2], BL[nb][kb*2+1]);
                mma16816(c[nb][0], c[nb][1], c[nb][2], c[nb][3],
                         l0, l1, l2, l3, BH[nb][kb*2], BH[nb][kb*2+1]);
            }
        }
#pragma unroll
        for (int nb = 0; nb < 4; nb++)
            *(float4*)&d1buf[((tid * 2 + mbi) * 4 + nb) * 4] =
                make_float4(c[nb][0], c[nb][1], c[nb][2], c[nb][3]);
    }

    // ---- load B fragments for GEMM2 (Wv), overwrite ----
#pragma unroll
    for (int nb = 0; nb < 4; nb++) {
        const uint4* bp = (const uint4*)g_BF + ((size_t)((ng * 4 + nb) * 2 + 1) * 32 + lane) * 4;
        uint4 q0 = bp[0], q1 = bp[1], q2 = bp[2], q3 = bp[3];
        BH[nb][0]=q0.x; BH[nb][1]=q0.y; BH[nb][2]=q0.z; BH[nb][3]=q0.w;
        BH[nb][4]=q1.x; BH[nb][5]=q1.y; BH[nb][6]=q1.z; BH[nb][7]=q1.w;
        BL[nb][0]=q2.x; BL[nb][1]=q2.y; BL[nb][2]=q2.z; BL[nb][3]=q2.w;
        BL[nb][4]=q3.x; BL[nb][5]=q3.y; BL[nb][6]=q3.z; BL[nb][7]=q3.w;
    }

    float2 bvv[4];
#pragma unroll
    for (int nb = 0; nb < 4; nb++)
        bvv[nb] = *(const float2*)(bv + (ng * 4 + nb) * 8 + 2 * t);

    // ---- GEMM2 + fused softmax epilogue ----
#pragma unroll
    for (int mbi = 0; mbi < 2; mbi++) {
        int b = mg * 2 + mbi;
        float c[4][4];
#pragma unroll
        for (int nb = 0; nb < 4; nb++)
#pragma unroll
            for (int j = 0; j < 4; j++) c[nb][j] = 0.f;
        unsigned rowoff = (unsigned)(b * 16 + lmrow) * 128 + lmcol;
#pragma unroll
        for (int kb = 0; kb < 4; kb++) {
            unsigned off = SWZ128(rowoff + kb * 32);
            uint32_t a0, a1, a2, a3, l0, l1, l2, l3;
            ldsm_x4(a0, a1, a2, a3, sb_vh + off);
            ldsm_x4(l0, l1, l2, l3, sb_vl + off);
#pragma unroll
            for (int nb = 0; nb < 4; nb++) {
                mma16816(c[nb][0], c[nb][1], c[nb][2], c[nb][3],
                         a0, a1, a2, a3, BH[nb][kb*2], BH[nb][kb*2+1]);
                mma16816(c[nb][0], c[nb][1], c[nb][2], c[nb][3],
                         a0, a1, a2, a3, BL[nb][kb*2], BL[nb][kb*2+1]);
                mma16816(c[nb][0], c[nb][1], c[nb][2], c[nb][3],
                         l0, l1, l2, l3, BH[nb][kb*2], BH[nb][kb*2+1]);
            }
        }
        int mka = smask[b * 16 + gg];
        int mkb = smask[b * 16 + gg + 8];
#pragma unroll
        for (int nb = 0; nb < 4; nb++) {
            float4 d1 = *(float4*)&d1buf[((tid * 2 + mbi) * 4 + nb) * 4];
            float e0 = mka ? -1e12f : d1.x;
            float e1 = mka ? -1e12f : d1.y;
            float e2 = mkb ? -1e12f : d1.z;
            float e3 = mkb ? -1e12f : d1.w;

            float mx0 = fmaxf(e0, e2), mx1 = fmaxf(e1, e3);
#pragma unroll
            for (int s = 4; s < 32; s <<= 1) {
                mx0 = fmaxf(mx0, __shfl_xor_sync(0xffffffffu, mx0, s));
                mx1 = fmaxf(mx1, __shfl_xor_sync(0xffffffffu, mx1, s));
            }
            float p0 = __expf(e0 - mx0), p2 = __expf(e2 - mx0);
            float p1 = __expf(e1 - mx1), p3 = __expf(e3 - mx1);
            float s0 = p0 + p2, s1 = p1 + p3;
            float w0 = p0 * c[nb][0] + p2 * c[nb][2];
            float w1 = p1 * c[nb][1] + p3 * c[nb][3];
#pragma unroll
            for (int s = 4; s < 32; s <<= 1) {
                s0 += __shfl_xor_sync(0xffffffffu, s0, s);
                s1 += __shfl_xor_sync(0xffffffffu, s1, s);
                w0 += __shfl_xor_sync(0xffffffffu, w0, s);
                w1 += __shfl_xor_sync(0xffffffffu, w1, s);
            }
            if (lane < 4) {
                float2 o = make_float2(w0 / s0 + bvv[nb].x, w1 / s1 + bvv[nb].y);
                *(float2*)(g_RES + (size_t)(m0 + b) * CH + (ng * 4 + nb) * 8 + 2 * t) = o;
            }
        }
    }
}

// ---------------------------------------------------------------------------
// Kernel 4: out = g_RES @ Wt + bt
// ---------------------------------------------------------------------------
__global__ __launch_bounds__(256) void outproj_kernel(
    const float* __restrict__ Wt, const float* __restrict__ bt,
    float* __restrict__ out)
{
    __shared__ __align__(16) float WT[CH * WST];
    __shared__ __align__(16) float rowbuf[8][8 * CH];
    __shared__ float bsh[CH];

    int tid = threadIdx.x, lane = tid & 31, wid = tid >> 5;

    for (int i = tid; i < CH * CH; i += 256) {
        int t = i >> 6, c = i & 63;
        WT[c * WST + t] = Wt[i];
    }
    if (tid < CH) bsh[tid] = bt[tid];
    __syncthreads();

    int r0 = blockIdx.x * 64 + wid * 8;
    float* rb = &rowbuf[wid][0];
#pragma unroll
    for (int j = 0; j < 8; j++) {
        ((float2*)(rb + j * CH))[lane] =
            ((const float2*)(g_RES + (size_t)(r0 + j) * CH))[lane];
    }
    __syncwarp();

    unsigned long long accA[8], accB[8];
#pragma unroll
    for (int j = 0; j < 8; j++) { accA[j] = 0ull; accB[j] = 0ull; }
    const float* wr0 = WT + lane * WST;
    const float* wr1 = WT + (lane + 32) * WST;

#pragma unroll
    for (int t4 = 0; t4 < CH; t4 += 4) {
        ulonglong2 wa = *reinterpret_cast<const ulonglong2*>(wr0 + t4);
        ulonglong2 wb = *reinterpret_cast<const ulonglong2*>(wr1 + t4);
#pragma unroll
        for (int j = 0; j < 8; j++) {
            ulonglong2 hp = *reinterpret_cast<const ulonglong2*>(rb + j * CH + t4);
            accA[j] = fma2(hp.x, wa.x, accA[j]);
            accA[j] = fma2(hp.y, wa.y, accA[j]);
            accB[j] = fma2(hp.x, wb.x, accB[j]);
            accB[j] = fma2(hp.y, wb.y, accB[j]);
        }
    }
#pragma unroll
    for (int j = 0; j < 8; j++) {
        out[(size_t)(r0 + j) * CH + lane]      = hsum2(accA[j]) + bsh[lane];
        out[(size_t)(r0 + j) * CH + 32 + lane] = hsum2(accB[j]) + bsh[lane + 32];
    }
}

// ---------------------------------------------------------------------------
// kernel_launch
// ---------------------------------------------------------------------------
extern "C" void kernel_launch(void* const* d_in, const int* in_sizes, int n_in,
                              void* d_out, int out_size)
{
    const float* q      = (const float*)d_in[0];
    const float* k      = (const float*)d_in[1];
    const float* value  = (const float*)d_in[2];
    const float* q_pos  = (const float*)d_in[3];
    const float* k_pos  = (const float*)d_in[4];
    const unsigned char* mask = (const unsigned char*)d_in[5];
    const int*   knn    = (const int*)d_in[6];
    const float* Wqk    = (const float*)d_in[8];
    const float* Wv     = (const float*)d_in[10];
    const float* bv     = (const float*)d_in[11];
    const float* Wg1    = (const float*)d_in[12];
    const float* bg1    = (const float*)d_in[13];
    const float* Wg2    = (const float*)d_in[14];
    const float* Wt     = (const float*)d_in[16];
    const float* bt     = (const float*)d_in[17];
    float* out = (float*)d_out;

    cudaFuncSetAttribute(attn_mma_kernel,
                         cudaFuncAttributeMaxDynamicSharedMemorySize, ATT_SMEM);

    detect_mask_kernel<<<1, 1024>>>(mask);
    compute_A_kernel<<<8, 512>>>(Wqk, Wg1);
    prep_bfrag_kernel<<<32, 256>>>(Wg2, Wv);
    project_kernel<<<(M_Q + N_K) / 64, 256>>>(q, q_pos, k, k_pos, bg1);
    attn_mma_kernel<<<M_Q / 8, 256, ATT_SMEM>>>(value, mask, knn, bv);
    outproj_kernel<<<M_Q / 64, 256>>>(Wt, bt, out);
}

// round 9
// speedup vs baseline: 1.1987x; 1.1987x over previous
#include <cuda_runtime.h>
#include <cuda_bf16.h>
#include <cstdint>

// Problem constants
#define M_Q 65536
#define N_K 65536
#define KNB 16
#define CH  64
#define WST 68

// ---------------------------------------------------------------------------
// Device-global scratch
// ---------------------------------------------------------------------------
__device__ float g_A  [CH * CH];
__device__ float g_QG [M_Q * CH];
__device__ float g_KG [N_K * CH];
__device__ float g_RES[M_Q * CH];
__device__ int   g_mask_mode;
// B fragments: [nb(8)][gemm(2)][lane(32)][16 words]; w: split=w>>3, kb=(w>>1)&3, r=w&1
__device__ unsigned int g_BF[8 * 2 * 32 * 16];

#define SWZ128(x) ((x) ^ (((x) >> 3) & 0x70))

// ---------------------------------------------------------------------------
// fp32x2 helpers
// ---------------------------------------------------------------------------
__device__ __forceinline__ unsigned long long fma2(unsigned long long a,
                                                   unsigned long long b,
                                                   unsigned long long c) {
    unsigned long long d;
    asm("fma.rn.f32x2 %0, %1, %2, %3;" : "=l"(d) : "l"(a), "l"(b), "l"(c));
    return d;
}
__device__ __forceinline__ float hsum2(unsigned long long v) {
    float lo, hi;
    asm("mov.b64 {%0, %1}, %2;" : "=f"(lo), "=f"(hi) : "l"(v));
    return lo + hi;
}

// ---------------------------------------------------------------------------
// bf16 split helpers
// ---------------------------------------------------------------------------
__device__ __forceinline__ unsigned int pack_hi(float x0, float x1,
                                                float& r0, float& r1) {
    __nv_bfloat16 b0 = __float2bfloat16(x0), b1 = __float2bfloat16(x1);
    r0 = x0 - __bfloat162float(b0);
    r1 = x1 - __bfloat162float(b1);
    return ((unsigned int)__bfloat16_as_ushort(b1) << 16) |
           (unsigned int)__bfloat16_as_ushort(b0);
}
__device__ __forceinline__ unsigned int pack_lo(float r0, float r1) {
    return ((unsigned int)__bfloat16_as_ushort(__float2bfloat16(r1)) << 16) |
           (unsigned int)__bfloat16_as_ushort(__float2bfloat16(r0));
}

// ---------------------------------------------------------------------------
// mma.sync / ldmatrix wrappers
// ---------------------------------------------------------------------------
__device__ __forceinline__ uint32_t smem_u32(const void* p) {
    uint32_t a;
    asm("{ .reg .u64 t; cvta.to.shared.u64 t, %1; cvt.u32.u64 %0, t; }"
        : "=r"(a) : "l"(p));
    return a;
}
__device__ __forceinline__ void ldsm_x4(uint32_t& a0, uint32_t& a1,
                                        uint32_t& a2, uint32_t& a3, uint32_t addr) {
    asm volatile("ldmatrix.sync.aligned.m8n8.x4.shared.b16 {%0,%1,%2,%3}, [%4];"
                 : "=r"(a0), "=r"(a1), "=r"(a2), "=r"(a3) : "r"(addr));
}
__device__ __forceinline__ void mma16816(float& c0, float& c1, float& c2, float& c3,
                                         uint32_t a0, uint32_t a1, uint32_t a2,
                                         uint32_t a3, uint32_t b0, uint32_t b1) {
    asm volatile(
        "mma.sync.aligned.m16n8k16.row.col.f32.bf16.bf16.f32 "
        "{%0,%1,%2,%3}, {%4,%5,%6,%7}, {%8,%9}, {%0,%1,%2,%3};"
        : "+f"(c0), "+f"(c1), "+f"(c2), "+f"(c3)
        : "r"(a0), "r"(a1), "r"(a2), "r"(a3), "r"(b0), "r"(b1));
}

// ---------------------------------------------------------------------------
// Kernel 0: detect mask dtype
// ---------------------------------------------------------------------------
__global__ void detect_mask_kernel(const unsigned char* __restrict__ mask) {
    __shared__ int sA, sB;
    int tid = threadIdx.x;
    if (tid == 0) { sA = 0; sB = 0; }
    __syncthreads();
    const uint4* p = (const uint4*)mask;
    int nvec = (M_Q * KNB) / 16;
    int fA = 0, fB = 0;
    for (int i = tid; i < nvec; i += blockDim.x) {
        uint4 v = p[i];
        unsigned w[4] = {v.x, v.y, v.z, v.w};
#pragma unroll
        for (int j = 0; j < 4; j++) {
            if ((w[j] >> 24) == 0x3fu) fA = 1;
            if (w[j] & 0x00ffff00u)    fB = 1;
            if ((w[j] >> 24) && ((w[j] >> 24) != 0x3fu)) fB = 1;
        }
    }
    if (fA) atomicOr(&sA, 1);
    if (fB) atomicOr(&sB, 1);
    __syncthreads();
    if (tid == 0) g_mask_mode = sA ? 2 : (sB ? 0 : 1);
}

// ---------------------------------------------------------------------------
// Kernel 1: A = Wqk @ Wg1
// ---------------------------------------------------------------------------
__global__ void compute_A_kernel(const float* __restrict__ Wqk,
                                 const float* __restrict__ Wg1) {
    int t = blockIdx.x * blockDim.x + threadIdx.x;
    int r = t >> 6, c = t & 63;
    float s = 0.f;
#pragma unroll
    for (int u = 0; u < CH; u++) s += Wqk[r * CH + u] * Wg1[u * CH + c];
    g_A[t] = s;
}

// ---------------------------------------------------------------------------
// Kernel 1b: precompute B fragments (hi/lo split) for Wg2 and Wv
// ---------------------------------------------------------------------------
__global__ void prep_bfrag_kernel(const float* __restrict__ Wg2,
                                  const float* __restrict__ Wv) {
    int idx = blockIdx.x * 256 + threadIdx.x;       // 0..8191
    int nb   = idx >> 10;
    int rem  = idx & 1023;
    int gm   = rem >> 9;
    int rem2 = rem & 511;
    int lane = rem2 >> 4;
    int w    = rem2 & 15;
    int split = w >> 3, kb = (w >> 1) & 3, r = w & 1;
    int t = lane & 3, gg = lane >> 2;
    int k0 = kb * 16 + 2 * t + (r ? 8 : 0);
    int n  = nb * 8 + gg;
    const float* W = gm ? Wv : Wg2;
    float w0 = W[k0 * CH + n];
    float w1 = W[(k0 + 1) * CH + n];
    unsigned int word;
    if (split == 0) { float r0, r1; word = pack_hi(w0, w1, r0, r1); }
    else {
        __nv_bfloat16 b0 = __float2bfloat16(w0), b1 = __float2bfloat16(w1);
        word = pack_lo(w0 - __bfloat162float(b0), w1 - __bfloat162float(b1));
    }
    g_BF[idx] = word;
}

// ---------------------------------------------------------------------------
// Kernel 2: merged projection (fma2 path, unchanged)
// ---------------------------------------------------------------------------
__global__ __launch_bounds__(256) void project_kernel(
    const float* __restrict__ q, const float* __restrict__ q_pos,
    const float* __restrict__ k, const float* __restrict__ k_pos,
    const float* __restrict__ bg1)
{
    __shared__ __align__(16) float AT[CH * WST];
    __shared__ __align__(16) float rowbuf[8][8 * CH];
    __shared__ float bsh[CH];

    int tid = threadIdx.x, lane = tid & 31, wid = tid >> 5;

    for (int i = tid; i < CH * CH; i += 256) {
        int t = i >> 6, c = i & 63;
        AT[c * WST + t] = g_A[i];
    }
    if (tid < CH) bsh[tid] = bg1[tid];
    __syncthreads();

    int row0 = blockIdx.x * 64 + wid * 8;
    bool is_q = row0 < M_Q;
    const float* src = is_q ? q : k;
    const float* pos = is_q ? q_pos : k_pos;
    float* dst       = is_q ? g_QG : g_KG;
    int r0 = is_q ? row0 : row0 - M_Q;

    float* rb = &rowbuf[wid][0];
#pragma unroll
    for (int j = 0; j < 8; j++) {
        const float2* s2 = (const float2*)(src + (size_t)(r0 + j) * CH);
        const float2* p2 = (const float2*)(pos + (size_t)(r0 + j) * CH);
        float2 a = s2[lane], b = p2[lane];
        ((float2*)(rb + j * CH))[lane] = make_float2(a.x + b.x, a.y + b.y);
    }
    __syncwarp();

    unsigned long long accA[8], accB[8];
#pragma unroll
    for (int j = 0; j < 8; j++) { accA[j] = 0ull; accB[j] = 0ull; }
    const float* wr0 = AT + lane * WST;
    const float* wr1 = AT + (lane + 32) * WST;

#pragma unroll
    for (int t4 = 0; t4 < CH; t4 += 4) {
        ulonglong2 wa = *reinterpret_cast<const ulonglong2*>(wr0 + t4);
        ulonglong2 wb = *reinterpret_cast<const ulonglong2*>(wr1 + t4);
#pragma unroll
        for (int j = 0; j < 8; j++) {
            ulonglong2 hp = *reinterpret_cast<const ulonglong2*>(rb + j * CH + t4);
            accA[j] = fma2(hp.x, wa.x, accA[j]);
            accA[j] = fma2(hp.y, wa.y, accA[j]);
            accB[j] = fma2(hp.x, wb.x, accB[j]);
            accB[j] = fma2(hp.y, wb.y, accB[j]);
        }
    }
    float b0 = is_q ? bsh[lane] : 0.f;
    float b1 = is_q ? bsh[lane + 32] : 0.f;
#pragma unroll
    for (int j = 0; j < 8; j++) {
        dst[(size_t)(r0 + j) * CH + lane]      = hsum2(accA[j]) + b0;
        dst[(size_t)(r0 + j) * CH + 32 + lane] = hsum2(accB[j]) + b1;
    }
}

// ---------------------------------------------------------------------------
// Kernel 3: HMMA attention, 2-D warp decomposition.
//   Warp = (m-group mg of 2 m-blocks, n-group ng of 4 n-blocks).
//   D1 smem buffer now LANE-MAJOR -> conflict-free STS/LDS.128.
// smem: h_hi 16K | h_lo 16K | v_hi 16K | v_lo 16K | mask 512 | D1buf 32K
// ---------------------------------------------------------------------------
#define SM_HH 0
#define SM_HL 16384
#define SM_VH 32768
#define SM_VL 49152
#define SM_MK 65536
#define SM_D1 66048
#define ATT_SMEM (66048 + 32768)

__global__ __launch_bounds__(256, 2) void attn_mma_kernel(
    const float* __restrict__ value, const unsigned char* __restrict__ mask,
    const int* __restrict__ knn, const float* __restrict__ bv)
{
    extern __shared__ __align__(1024) char smc[];
    int*   smask = (int*)(smc + SM_MK);
    float* d1buf = (float*)(smc + SM_D1);

    int tid = threadIdx.x, lane = tid & 31, wid = tid >> 5;
    int m0 = blockIdx.x * 8;
    int t = lane & 3, gg = lane >> 2;

    uint32_t sb_hh = smem_u32(smc + SM_HH);
    uint32_t sb_hl = smem_u32(smc + SM_HL);
    uint32_t sb_vh = smem_u32(smc + SM_VH);
    uint32_t sb_vl = smem_u32(smc + SM_VL);

    // ---- mask preload ----
    if (tid < 128) {
        int qloc = tid >> 4, e = tid & 15;
        size_t ix = (size_t)(m0 + qloc) * KNB + e;
        int mmode = g_mask_mode, mk;
        if (mmode == 0)      mk = mask[ix] != 0;
        else if (mmode == 1) mk = ((const int*)mask)[ix] != 0;
        else                 mk = ((const float*)mask)[ix] != 0.f;
        smask[tid] = mk;
    }

    // ---- build h AND value tiles upfront (warp w = query w) ----
    int mq = m0 + wid;
    int nbr = 0;
    if (lane < KNB) nbr = knn[(size_t)M_Q * KNB + (size_t)mq * KNB + lane];
    float2 qg = ((const float2*)(g_QG + (size_t)mq * CH))[lane];

#pragma unroll
    for (int e = 0; e < KNB; e++) {
        int n = __shfl_sync(0xffffffffu, nbr, e);
        float2 kg = ((const float2*)(g_KG + (size_t)n * CH))[lane];
        float x0 = fmaxf(qg.x - kg.x, 0.f), x1 = fmaxf(qg.y - kg.y, 0.f);
        unsigned off = SWZ128((unsigned)((wid * KNB + e) * 128 + lane * 4));
        float r0, r1;
        unsigned hiw = pack_hi(x0, x1, r0, r1);
        *(unsigned*)(smc + SM_HH + off) = hiw;
        *(unsigned*)(smc + SM_HL + off) = pack_lo(r0, r1);
    }
#pragma unroll
    for (int e = 0; e < KNB; e++) {
        float2 v2 = ((const float2*)(value + ((size_t)mq * KNB + e) * CH))[lane];
        unsigned off = SWZ128((unsigned)((wid * KNB + e) * 128 + lane * 4));
        float r0, r1;
        unsigned hiw = pack_hi(v2.x, v2.y, r0, r1);
        *(unsigned*)(smc + SM_VH + off) = hiw;
        *(unsigned*)(smc + SM_VL + off) = pack_lo(r0, r1);
    }
    __syncthreads();

    int mg = wid >> 1;       // m-group: m-blocks {2mg, 2mg+1}
    int ng = wid & 1;        // n-group: n-blocks [4ng, 4ng+4)

    unsigned lmrow = (unsigned)(lane & 15);
    unsigned lmcol = (unsigned)((lane >> 4) & 1) * 16;

    uint32_t BH[4][8], BL[4][8];

    // ---- load B fragments for GEMM1 (Wg2), 4 owned n-blocks ----
#pragma unroll
    for (int nb = 0; nb < 4; nb++) {
        const uint4* bp = (const uint4*)g_BF + ((size_t)((ng * 4 + nb) * 2 + 0) * 32 + lane) * 4;
        uint4 q0 = bp[0], q1 = bp[1], q2 = bp[2], q3 = bp[3];
        BH[nb][0]=q0.x; BH[nb][1]=q0.y; BH[nb][2]=q0.z; BH[nb][3]=q0.w;
        BH[nb][4]=q1.x; BH[nb][5]=q1.y; BH[nb][6]=q1.z; BH[nb][7]=q1.w;
        BL[nb][0]=q2.x; BL[nb][1]=q2.y; BL[nb][2]=q2.z; BL[nb][3]=q2.w;
        BL[nb][4]=q3.x; BL[nb][5]=q3.y; BL[nb][6]=q3.z; BL[nb][7]=q3.w;
    }

    // ---- GEMM1: logits -> D1 smem buffer (lane-major, conflict-free) ----
#pragma unroll
    for (int mbi = 0; mbi < 2; mbi++) {
        int b = mg * 2 + mbi;
        float c[4][4];
#pragma unroll
        for (int nb = 0; nb < 4; nb++)
#pragma unroll
            for (int j = 0; j < 4; j++) c[nb][j] = 0.f;
        unsigned rowoff = (unsigned)(b * 16 + lmrow) * 128 + lmcol;
#pragma unroll
        for (int kb = 0; kb < 4; kb++) {
            unsigned off = SWZ128(rowoff + kb * 32);
            uint32_t a0, a1, a2, a3, l0, l1, l2, l3;
            ldsm_x4(a0, a1, a2, a3, sb_hh + off);
            ldsm_x4(l0, l1, l2, l3, sb_hl + off);
#pragma unroll
            for (int nb = 0; nb < 4; nb++) {
                mma16816(c[nb][0], c[nb][1], c[nb][2], c[nb][3],
                         a0, a1, a2, a3, BH[nb][kb*2], BH[nb][kb*2+1]);
                mma16816(c[nb][0], c[nb][1], c[nb][2], c[nb][3],
                         a0, a1, a2, a3, BL[nb][kb*2], BL[nb][kb*2+1]);
                mma16816(c[nb][0], c[nb][1], c[nb][2], c[nb][3],
                         l0, l1, l2, l3, BH[nb][kb*2], BH[nb][kb*2+1]);
            }
        }
#pragma unroll
        for (int nb = 0; nb < 4; nb++)
            *(float4*)&d1buf[(((wid * 2 + mbi) * 4 + nb) * 32 + lane) * 4] =
                make_float4(c[nb][0], c[nb][1], c[nb][2], c[nb][3]);
    }

    // ---- load B fragments for GEMM2 (Wv), overwrite ----
#pragma unroll
    for (int nb = 0; nb < 4; nb++) {
        const uint4* bp = (const uint4*)g_BF + ((size_t)((ng * 4 + nb) * 2 + 1) * 32 + lane) * 4;
        uint4 q0 = bp[0], q1 = bp[1], q2 = bp[2], q3 = bp[3];
        BH[nb][0]=q0.x; BH[nb][1]=q0.y; BH[nb][2]=q0.z; BH[nb][3]=q0.w;
        BH[nb][4]=q1.x; BH[nb][5]=q1.y; BH[nb][6]=q1.z; BH[nb][7]=q1.w;
        BL[nb][0]=q2.x; BL[nb][1]=q2.y; BL[nb][2]=q2.z; BL[nb][3]=q2.w;
        BL[nb][4]=q3.x; BL[nb][5]=q3.y; BL[nb][6]=q3.z; BL[nb][7]=q3.w;
    }

    float2 bvv[4];
#pragma unroll
    for (int nb = 0; nb < 4; nb++)
        bvv[nb] = *(const float2*)(bv + (ng * 4 + nb) * 8 + 2 * t);

    // ---- GEMM2 + fused softmax epilogue ----
#pragma unroll
    for (int mbi = 0; mbi < 2; mbi++) {
        int b = mg * 2 + mbi;
        float c[4][4];
#pragma unroll
        for (int nb = 0; nb < 4; nb++)
#pragma unroll
            for (int j = 0; j < 4; j++) c[nb][j] = 0.f;
        unsigned rowoff = (unsigned)(b * 16 + lmrow) * 128 + lmcol;
#pragma unroll
        for (int kb = 0; kb < 4; kb++) {
            unsigned off = SWZ128(rowoff + kb * 32);
            uint32_t a0, a1, a2, a3, l0, l1, l2, l3;
            ldsm_x4(a0, a1, a2, a3, sb_vh + off);
            ldsm_x4(l0, l1, l2, l3, sb_vl + off);
#pragma unroll
            for (int nb = 0; nb < 4; nb++) {
                mma16816(c[nb][0], c[nb][1], c[nb][2], c[nb][3],
                         a0, a1, a2, a3, BH[nb][kb*2], BH[nb][kb*2+1]);
                mma16816(c[nb][0], c[nb][1], c[nb][2], c[nb][3],
                         a0, a1, a2, a3, BL[nb][kb*2], BL[nb][kb*2+1]);
                mma16816(c[nb][0], c[nb][1], c[nb][2], c[nb][3],
                         l0, l1, l2, l3, BH[nb][kb*2], BH[nb][kb*2+1]);
            }
        }
        int mka = smask[b * 16 + gg];
        int mkb = smask[b * 16 + gg + 8];
#pragma unroll
        for (int nb = 0; nb < 4; nb++) {
            float4 d1 = *(float4*)&d1buf[(((wid * 2 + mbi) * 4 + nb) * 32 + lane) * 4];
            float e0 = mka ? -1e12f : d1.x;
            float e1 = mka ? -1e12f : d1.y;
            float e2 = mkb ? -1e12f : d1.z;
            float e3 = mkb ? -1e12f : d1.w;

            float mx0 = fmaxf(e0, e2), mx1 = fmaxf(e1, e3);
#pragma unroll
            for (int s = 4; s < 32; s <<= 1) {
                mx0 = fmaxf(mx0, __shfl_xor_sync(0xffffffffu, mx0, s));
                mx1 = fmaxf(mx1, __shfl_xor_sync(0xffffffffu, mx1, s));
            }
            float p0 = __expf(e0 - mx0), p2 = __expf(e2 - mx0);
            float p1 = __expf(e1 - mx1), p3 = __expf(e3 - mx1);
            float s0 = p0 + p2, s1 = p1 + p3;
            float w0 = p0 * c[nb][0] + p2 * c[nb][2];
            float w1 = p1 * c[nb][1] + p3 * c[nb][3];
#pragma unroll
            for (int s = 4; s < 32; s <<= 1) {
                s0 += __shfl_xor_sync(0xffffffffu, s0, s);
                s1 += __shfl_xor_sync(0xffffffffu, s1, s);
                w0 += __shfl_xor_sync(0xffffffffu, w0, s);
                w1 += __shfl_xor_sync(0xffffffffu, w1, s);
            }
            if (lane < 4) {
                float2 o = make_float2(w0 / s0 + bvv[nb].x, w1 / s1 + bvv[nb].y);
                *(float2*)(g_RES + (size_t)(m0 + b) * CH + (ng * 4 + nb) * 8 + 2 * t) = o;
            }
        }
    }
}

// ---------------------------------------------------------------------------
// Kernel 4: out = g_RES @ Wt + bt
// ---------------------------------------------------------------------------
__global__ __launch_bounds__(256) void outproj_kernel(
    const float* __restrict__ Wt, const float* __restrict__ bt,
    float* __restrict__ out)
{
    __shared__ __align__(16) float WT[CH * WST];
    __shared__ __align__(16) float rowbuf[8][8 * CH];
    __shared__ float bsh[CH];

    int tid = threadIdx.x, lane = tid & 31, wid = tid >> 5;

    for (int i = tid; i < CH * CH; i += 256) {
        int t = i >> 6, c = i & 63;
        WT[c * WST + t] = Wt[i];
    }
    if (tid < CH) bsh[tid] = bt[tid];
    __syncthreads();

    int r0 = blockIdx.x * 64 + wid * 8;
    float* rb = &rowbuf[wid][0];
#pragma unroll
    for (int j = 0; j < 8; j++) {
        ((float2*)(rb + j * CH))[lane] =
            ((const float2*)(g_RES + (size_t)(r0 + j) * CH))[lane];
    }
    __syncwarp();

    unsigned long long accA[8], accB[8];
#pragma unroll
    for (int j = 0; j < 8; j++) { accA[j] = 0ull; accB[j] = 0ull; }
    const float* wr0 = WT + lane * WST;
    const float* wr1 = WT + (lane + 32) * WST;

#pragma unroll
    for (int t4 = 0; t4 < CH; t4 += 4) {
        ulonglong2 wa = *reinterpret_cast<const ulonglong2*>(wr0 + t4);
        ulonglong2 wb = *reinterpret_cast<const ulonglong2*>(wr1 + t4);
#pragma unroll
        for (int j = 0; j < 8; j++) {
            ulonglong2 hp = *reinterpret_cast<const ulonglong2*>(rb + j * CH + t4);
            accA[j] = fma2(hp.x, wa.x, accA[j]);
            accA[j] = fma2(hp.y, wa.y, accA[j]);
            accB[j] = fma2(hp.x, wb.x, accB[j]);
            accB[j] = fma2(hp.y, wb.y, accB[j]);
        }
    }
#pragma unroll
    for (int j = 0; j < 8; j++) {
        out[(size_t)(r0 + j) * CH + lane]      = hsum2(accA[j]) + bsh[lane];
        out[(size_t)(r0 + j) * CH + 32 + lane] = hsum2(accB[j]) + bsh[lane + 32];
    }
}

// ---------------------------------------------------------------------------
// kernel_launch
// ---------------------------------------------------------------------------
extern "C" void kernel_launch(void* const* d_in, const int* in_sizes, int n_in,
                              void* d_out, int out_size)
{
    const float* q      = (const float*)d_in[0];
    const float* k      = (const float*)d_in[1];
    const float* value  = (const float*)d_in[2];
    const float* q_pos  = (const float*)d_in[3];
    const float* k_pos  = (const float*)d_in[4];
    const unsigned char* mask = (const unsigned char*)d_in[5];
    const int*   knn    = (const int*)d_in[6];
    const float* Wqk    = (const float*)d_in[8];
    const float* Wv     = (const float*)d_in[10];
    const float* bv     = (const float*)d_in[11];
    const float* Wg1    = (const float*)d_in[12];
    const float* bg1    = (const float*)d_in[13];
    const float* Wg2    = (const float*)d_in[14];
    const float* Wt     = (const float*)d_in[16];
    const float* bt     = (const float*)d_in[17];
    float* out = (float*)d_out;

    cudaFuncSetAttribute(attn_mma_kernel,
                         cudaFuncAttributeMaxDynamicSharedMemorySize, ATT_SMEM);

    detect_mask_kernel<<<1, 1024>>>(mask);
    compute_A_kernel<<<8, 512>>>(Wqk, Wg1);
    prep_bfrag_kernel<<<32, 256>>>(Wg2, Wv);
    project_kernel<<<(M_Q + N_K) / 64, 256>>>(q, q_pos, k, k_pos, bg1);
    attn_mma_kernel<<<M_Q / 8, 256, ATT_SMEM>>>(value, mask, knn, bv);
    outproj_kernel<<<M_Q / 64, 256>>>(Wt, bt, out);
}